// round 15
// baseline (speedup 1.0000x reference)
#include <cuda_runtime.h>
#include <cuda_bf16.h>
#include <cuda_fp16.h>
#include <math.h>
#include <stdint.h>

#define N_ELEM 131072
#define C_DIM  512
#define G_DIM  4096
#define NOUT   1024     // Wf cols || Wg cols

// ---------------- scratch (device globals; no allocation allowed) ----------------
__device__ __nv_bfloat16 g_whi[(size_t)NOUT * C_DIM];     // 1 MB, K-major [n][k]
__device__ __nv_bfloat16 g_wlo[(size_t)NOUT * C_DIM];     // 1 MB
__device__ __nv_bfloat16 g_whh[(size_t)C_DIM * C_DIM];    // 0.5 MB, Wh hi, K-major
__device__ __nv_bfloat16 g_wlh[(size_t)C_DIM * C_DIM];    // 0.5 MB, Wh lo
__device__ __half g_eg[(size_t)N_ELEM * C_DIM];           // 128 MB (fp16)
__device__ float g_denom[G_DIM * C_DIM];                  // 8 MB (then reciprocal)
__device__ float g_y[G_DIM * C_DIM];                      // 8 MB
__device__ float g_yh[G_DIM * C_DIM];                     // 8 MB

#define MMA16816(d, a0, a1, a2, a3, b0, b1) \
    asm volatile("mma.sync.aligned.m16n8k16.row.col.f32.bf16.bf16.f32 " \
                 "{%0,%1,%2,%3}, {%4,%5,%6,%7}, {%8,%9}, {%0,%1,%2,%3};" \
                 : "+f"((d)[0]), "+f"((d)[1]), "+f"((d)[2]), "+f"((d)[3]) \
                 : "r"(a0), "r"(a1), "r"(a2), "r"(a3), "r"(b0), "r"(b1))

__device__ __forceinline__ uint32_t smem_u32(const void* p) {
    uint32_t a;
    asm("{ .reg .u64 t; cvta.to.shared.u64 t, %1; cvt.u32.u64 %0, t; }" : "=r"(a) : "l"(p));
    return a;
}
__device__ __forceinline__ void cp16(uint32_t saddr, const void* g) {
    asm volatile("cp.async.cg.shared.global [%0], [%1], 16;" :: "r"(saddr), "l"(g));
}

// ---------------- zero accumulators ----------------
__global__ void zero_kernel() {
    int i = blockIdx.x * blockDim.x + threadIdx.x;   // G*C/4
    float4 z = make_float4(0.f, 0.f, 0.f, 0.f);
    ((float4*)g_denom)[i] = z;
    ((float4*)g_y)[i] = z;
}

// ---------------- denom -> 1/denom (between the two gemm halves) ----------------
__global__ void rcp_kernel() {
    int i = blockIdx.x * blockDim.x + threadIdx.x;   // G*C/4
    float4 d = ((float4*)g_denom)[i];
    d.x = 1.0f / d.x;
    d.y = 1.0f / d.y;
    d.z = 1.0f / d.z;
    d.w = 1.0f / d.w;
    ((float4*)g_denom)[i] = d;
}

// ---------------- build Whi/Wlo [n=1024][k=512] K-major bf16 ----------------
__global__ void build_w_kernel(const float* __restrict__ Wf,
                               const float* __restrict__ Wg) {
    int i = blockIdx.x * blockDim.x + threadIdx.x;   // NOUT*C_DIM
    int n = i >> 9;
    int k = i & 511;
    const float* W = (n < 512) ? Wf : Wg;
    float w = W[(size_t)k * C_DIM + (n & 511)];
    __nv_bfloat16 hi = __float2bfloat16(w);
    g_whi[i] = hi;
    g_wlo[i] = __float2bfloat16(w - __bfloat162float(hi));
}

// ---------------- build Wh hi/lo [n=512][k=512] K-major bf16 ----------------
__global__ void build_wh_kernel(const float* __restrict__ Wh) {
    int i = blockIdx.x * blockDim.x + threadIdx.x;   // C_DIM*C_DIM
    int n = i >> 9;
    int k = i & 511;
    float w = Wh[(size_t)k * C_DIM + n];
    __nv_bfloat16 hi = __float2bfloat16(w);
    g_whh[i] = hi;
    g_wlh[i] = __float2bfloat16(w - __bfloat162float(hi));
}

// ---------------- mma.sync bf16-split GEMM halves ------------------------------
// BM=64 tile (was 128): acc 64->32 regs, A-staging 16->8 regs, launch_bounds
// (256,3) -> 3 CTAs/SM = 24 warps/SM for latency hiding. Fragment-contiguous
// A smem layout, B 80B-pitch cp.async path, MMA order, epilogues as R14.
#define SPITCH 40                       // B pitch in bf16 elems (80B)
#define A_TILE_BYTES 4224               // 8 blocks * 528B (64 rows)
#define B_TILE_BYTES 10240              // 128 rows * 80B
#define STG_BYTES (2 * A_TILE_BYTES + 2 * B_TILE_BYTES)   // 28928
#define B_OFF (2 * A_TILE_BYTES)        // BHI offset within stage

#define PRECOMP_A_OFFS()                                                      \
    uint32_t aoff[2][2];                                                      \
    _Pragma("unroll")                                                         \
    for (int i_ = 0; i_ < 2; i_++) {                                          \
        int u_ = tid + 256 * i_;                                              \
        int r_ = u_ >> 3, sq_ = u_ & 7;                                       \
        _Pragma("unroll")                                                     \
        for (int q_ = 0; q_ < 2; q_++) {                                      \
            int w_ = 2 * sq_ + q_;                                            \
            int s_ = w_ >> 3, rem_ = w_ & 7;                                  \
            int tg_ = rem_ & 3, kk_ = rem_ >> 2;                              \
            aoff[i_][q_] = (uint32_t)(((r_ >> 4) * 2 + s_) * 528 +            \
                                      ((r_ & 7) * 4 + tg_) * 16 +             \
                                      kk_ * 8 + ((r_ >> 3) & 1) * 4);         \
        }                                                                     \
    }

#define LOAD_A_IMPL(SRC, CH) do {                                             \
        const int kc_ = (CH) * 32;                                            \
        _Pragma("unroll")                                                     \
        for (int i_ = 0; i_ < 2; i_++) {                                      \
            int u_ = tid + i_ * 256;                                          \
            int r_ = u_ >> 3, s_ = u_ & 7;                                    \
            stg[i_] = *(const float4*)((SRC) + (size_t)(row0 + r_) * C_DIM + kc_ + s_ * 4); \
        }                                                                     \
    } while (0)

#define STORE_A_IMPL(BUF) do {                                                \
        char* ahi_ = (char*)sm + (BUF) * STG_BYTES;                           \
        char* alo_ = ahi_ + A_TILE_BYTES;                                     \
        _Pragma("unroll")                                                     \
        for (int i_ = 0; i_ < 2; i_++) {                                      \
            float4 v_ = stg[i_];                                              \
            __nv_bfloat162 h01_, h23_, l01_, l23_;                            \
            h01_.x = __float2bfloat16(v_.x); h01_.y = __float2bfloat16(v_.y); \
            h23_.x = __float2bfloat16(v_.z); h23_.y = __float2bfloat16(v_.w); \
            l01_.x = __float2bfloat16(v_.x - __bfloat162float(h01_.x));       \
            l01_.y = __float2bfloat16(v_.y - __bfloat162float(h01_.y));       \
            l23_.x = __float2bfloat16(v_.z - __bfloat162float(h23_.x));       \
            l23_.y = __float2bfloat16(v_.w - __bfloat162float(h23_.y));       \
            *(uint32_t*)(ahi_ + aoff[i_][0]) = *(uint32_t*)&h01_;             \
            *(uint32_t*)(ahi_ + aoff[i_][1]) = *(uint32_t*)&h23_;             \
            *(uint32_t*)(alo_ + aoff[i_][0]) = *(uint32_t*)&l01_;             \
            *(uint32_t*)(alo_ + aoff[i_][1]) = *(uint32_t*)&l23_;             \
        }                                                                     \
    } while (0)

#define LOAD_B_IMPL(WH, WL, KSTRIDE, BUF, CH) do {                            \
        const int kc_ = (CH) * 32;                                            \
        uint32_t bhi_ = smem_u32((char*)sm + (BUF) * STG_BYTES + B_OFF);      \
        uint32_t blo_ = bhi_ + B_TILE_BYTES;                                  \
        _Pragma("unroll")                                                     \
        for (int i_ = 0; i_ < 2; i_++) {                                      \
            int u_ = tid + i_ * 256;                                          \
            int nr_ = u_ >> 2, ch_ = u_ & 3;                                  \
            size_t go_ = (size_t)(n0g + nr_) * (KSTRIDE) + kc_ + ch_ * 8;     \
            uint32_t so_ = nr_ * (SPITCH * 2) + ch_ * 16;                     \
            cp16(bhi_ + so_, (WH) + go_);                                     \
            cp16(blo_ + so_, (WL) + go_);                                     \
        }                                                                     \
        asm volatile("cp.async.commit_group;" ::: "memory");                  \
    } while (0)

#define MAINLOOP_BODY(ASRC, WH, WL, KSTRIDE)                                  \
    LOAD_B_IMPL(WH, WL, KSTRIDE, 0, 0);                                       \
    LOAD_A_IMPL(ASRC, 0);                                                     \
    STORE_A_IMPL(0);                                                          \
    asm volatile("cp.async.wait_group 0;" ::: "memory");                      \
    __syncthreads();                                                          \
    for (int it = 0; it < 16; it++) {                                         \
        const int cur = it & 1;                                               \
        if (it + 1 < 16) {                                                    \
            LOAD_B_IMPL(WH, WL, KSTRIDE, cur ^ 1, it + 1);                    \
            LOAD_A_IMPL(ASRC, it + 1);                                        \
        }                                                                     \
        const char* Ab = (const char*)sm + cur * STG_BYTES;                   \
        const __nv_bfloat16* Bhi = (const __nv_bfloat16*)(Ab + B_OFF);        \
        const __nv_bfloat16* Blo = (const __nv_bfloat16*)(Ab + B_OFF + B_TILE_BYTES); \
        _Pragma("unroll")                                                     \
        for (int s = 0; s < 2; s++) {                                         \
            const int k0 = s * 16 + 2 * tig;                                  \
            uint32_t bH[4][2], bL[4][2];                                      \
            _Pragma("unroll")                                                 \
            for (int nt = 0; nt < 4; nt++) {                                  \
                const int rn = n_base + nt * 8 + gid;                         \
                bH[nt][0] = *(const uint32_t*)(Bhi + rn * SPITCH + k0);       \
                bH[nt][1] = *(const uint32_t*)(Bhi + rn * SPITCH + k0 + 8);   \
                bL[nt][0] = *(const uint32_t*)(Blo + rn * SPITCH + k0);       \
                bL[nt][1] = *(const uint32_t*)(Blo + rn * SPITCH + k0 + 8);   \
            }                                                                 \
            _Pragma("unroll")                                                 \
            for (int t = 0; t < 2; t++) {                                     \
                const uint32_t ar = (uint32_t)((((wm * 2 + t) * 2 + s) * 528) + l * 16); \
                uint4 qh = *(const uint4*)(Ab + ar);                          \
                uint4 ql = *(const uint4*)(Ab + A_TILE_BYTES + ar);           \
                _Pragma("unroll")                                             \
                for (int nt = 0; nt < 4; nt++)                                \
                    MMA16816(acc[t][nt], qh.x, qh.y, qh.z, qh.w,              \
                             bH[nt][0], bH[nt][1]);                           \
                _Pragma("unroll")                                             \
                for (int nt = 0; nt < 4; nt++)                                \
                    MMA16816(acc[t][nt], qh.x, qh.y, qh.z, qh.w,              \
                             bL[nt][0], bL[nt][1]);                           \
                _Pragma("unroll")                                             \
                for (int nt = 0; nt < 4; nt++)                                \
                    MMA16816(acc[t][nt], ql.x, ql.y, ql.z, ql.w,              \
                             bH[nt][0], bH[nt][1]);                           \
            }                                                                 \
        }                                                                     \
        if (it + 1 < 16) {                                                    \
            STORE_A_IMPL(cur ^ 1);                                            \
            asm volatile("cp.async.wait_group 0;" ::: "memory");              \
        }                                                                     \
        __syncthreads();                                                      \
    }

template <bool IS_G>
__global__ __launch_bounds__(256, 3)
void gemm_half(const float* __restrict__ x, const int* __restrict__ ix,
               const float* __restrict__ bias) {
    extern __shared__ __nv_bfloat16 sm[];

    const int tid  = threadIdx.x;
    const int l    = tid & 31;
    const int warp = tid >> 5;
    const int bx   = blockIdx.x;          // 0..3 -> 128-col stripe of this half
    const int row0 = blockIdx.y * 64;
    const int n0g  = (IS_G ? 512 : 0) + bx * 128;

    const int wm = warp >> 2;             // 0..1
    const int wn = warp & 3;              // 0..3
    const int n_base = wn * 32;
    const int gid = l >> 2, tig = l & 3;

    float acc[2][4][4];
#pragma unroll
    for (int t = 0; t < 2; t++)
#pragma unroll
        for (int n = 0; n < 4; n++)
#pragma unroll
            for (int r = 0; r < 4; r++) acc[t][n][r] = 0.f;

    float4 stg[2];
    PRECOMP_A_OFFS()

    MAINLOOP_BODY(x, g_whi, g_wlo, C_DIM)

    // ---- epilogue ----
#pragma unroll
    for (int t = 0; t < 2; t++) {
#pragma unroll
        for (int h = 0; h < 2; h++) {
            const int m = row0 + wm * 32 + t * 16 + gid + h * 8;
            const int grp = ix[m];
#pragma unroll
            for (int nt = 0; nt < 4; nt++) {
                const int cg = n0g + n_base + nt * 8 + 2 * tig;
                const int cw = cg & 511;
                float v0 = acc[t][nt][2 * h]     + bias[cw];
                float v1 = acc[t][nt][2 * h + 1] + bias[cw + 1];
                if (IS_G) {
                    v0 = __expf(v0);
                    v1 = __expf(v1);
                    __half2 eq = __floats2half2_rn(v0, v1);
                    *(__half2*)&g_eg[(size_t)m * C_DIM + cw] = eq;
                    float q0 = __half2float(__low2half(eq));
                    float q1 = __half2float(__high2half(eq));
                    float* dp = &g_denom[(size_t)grp * C_DIM + cw];
                    atomicAdd(dp,     q0);
                    atomicAdd(dp + 1, q1);
                } else {
                    __half2 eh = *(const __half2*)&g_eg[(size_t)m * C_DIM + cw];
                    float2 e = __half22float2(eh);
                    float2 d = *(const float2*)&g_denom[(size_t)grp * C_DIM + cw]; // reciprocal
                    float* yp = &g_y[(size_t)grp * C_DIM + cw];
                    atomicAdd(yp,     v0 * e.x * d.x);
                    atomicAdd(yp + 1, v1 * e.y * d.y);
                }
            }
        }
    }
}

// ---------------- yh = y @ Wh + bh via bf16-split mma (same mainloop) ----------
__global__ __launch_bounds__(256, 3)
void gemm_h_mma(const float* __restrict__ bh) {
    extern __shared__ __nv_bfloat16 sm[];

    const int tid  = threadIdx.x;
    const int l    = tid & 31;
    const int warp = tid >> 5;
    const int bx   = blockIdx.x;          // 0..3 -> 128-col stripe of 512
    const int row0 = blockIdx.y * 64;     // 0..63 row blocks of G_DIM
    const int n0g  = bx * 128;

    const int wm = warp >> 2;
    const int wn = warp & 3;
    const int n_base = wn * 32;
    const int gid = l >> 2, tig = l & 3;

    float acc[2][4][4];
#pragma unroll
    for (int t = 0; t < 2; t++)
#pragma unroll
        for (int n = 0; n < 4; n++)
#pragma unroll
            for (int r = 0; r < 4; r++) acc[t][n][r] = 0.f;

    float4 stg[2];
    PRECOMP_A_OFFS()

    MAINLOOP_BODY(g_y, g_whh, g_wlh, C_DIM)

    // ---- epilogue: bias + store ----
#pragma unroll
    for (int t = 0; t < 2; t++) {
#pragma unroll
        for (int h = 0; h < 2; h++) {
            const int m = row0 + wm * 32 + t * 16 + gid + h * 8;
#pragma unroll
            for (int nt = 0; nt < 4; nt++) {
                const int cw = n0g + n_base + nt * 8 + 2 * tig;
                float v0 = acc[t][nt][2 * h]     + bh[cw];
                float v1 = acc[t][nt][2 * h + 1] + bh[cw + 1];
                *(float2*)&g_yh[(size_t)m * C_DIM + cw] = make_float2(v0, v1);
            }
        }
    }
}

// ---------------- out[n] = yh[ix[n]] ----------------
__global__ void gather_kernel(const int* __restrict__ ix, float* __restrict__ out) {
    size_t idx = (size_t)blockIdx.x * blockDim.x + threadIdx.x;  // N*C/4
    int n  = (int)(idx >> 7);
    int cq = (int)(idx & 127) << 2;
    int g  = ix[n];
    *(float4*)&out[((size_t)n << 9) + cq] = *(const float4*)&g_yh[((size_t)g << 9) + cq];
}

extern "C" void kernel_launch(void* const* d_in, const int* in_sizes, int n_in,
                              void* d_out, int out_size) {
    const float* x  = (const float*)d_in[0];
    const int*   ix = (const int*)d_in[1];
    const float* Wf = (const float*)d_in[2];
    const float* bf = (const float*)d_in[3];
    const float* Wg = (const float*)d_in[4];
    const float* bg = (const float*)d_in[5];
    const float* Wh = (const float*)d_in[6];
    const float* bh = (const float*)d_in[7];
    float* out = (float*)d_out;

    const int SMEM = 2 * STG_BYTES;   // 57856 bytes
    cudaFuncSetAttribute(gemm_half<true>,  cudaFuncAttributeMaxDynamicSharedMemorySize, SMEM);
    cudaFuncSetAttribute(gemm_half<false>, cudaFuncAttributeMaxDynamicSharedMemorySize, SMEM);
    cudaFuncSetAttribute(gemm_h_mma,       cudaFuncAttributeMaxDynamicSharedMemorySize, SMEM);

    zero_kernel<<<(G_DIM * C_DIM / 4) / 256, 256>>>();
    build_w_kernel<<<(NOUT * C_DIM) / 256, 256>>>(Wf, Wg);
    build_wh_kernel<<<(C_DIM * C_DIM) / 256, 256>>>(Wh);

    dim3 g1(4, N_ELEM / 64);
    gemm_half<true><<<g1, 256, SMEM>>>(x, ix, bg);    // eg(fp16) + denom
    rcp_kernel<<<(G_DIM * C_DIM / 4) / 256, 256>>>(); // denom -> 1/denom
    gemm_half<false><<<g1, 256, SMEM>>>(x, ix, bf);   // fx, fused aggregation

    dim3 g2(4, G_DIM / 64);
    gemm_h_mma<<<g2, 256, SMEM>>>(bh);

    gather_kernel<<<(N_ELEM * (C_DIM / 4)) / 256, 256>>>(ix, out);
}

// round 16
// speedup vs baseline: 1.0698x; 1.0698x over previous
#include <cuda_runtime.h>
#include <cuda_bf16.h>
#include <cuda_fp16.h>
#include <math.h>
#include <stdint.h>

#define N_ELEM 131072
#define C_DIM  512
#define G_DIM  4096
#define NOUT   1024     // Wf cols || Wg cols

// ---------------- scratch (device globals; no allocation allowed) ----------------
// W buffers are stored FRAGMENT-PERMUTED (see build_w_kernel).
__device__ __nv_bfloat16 g_whi[(size_t)NOUT * C_DIM];     // 1 MB
__device__ __nv_bfloat16 g_wlo[(size_t)NOUT * C_DIM];     // 1 MB
__device__ __nv_bfloat16 g_whh[(size_t)C_DIM * C_DIM];    // 0.5 MB (Wh hi)
__device__ __nv_bfloat16 g_wlh[(size_t)C_DIM * C_DIM];    // 0.5 MB (Wh lo)
__device__ __half g_eg[(size_t)N_ELEM * C_DIM];           // 128 MB (fp16)
__device__ float g_denom[G_DIM * C_DIM];                  // 8 MB (then reciprocal)
__device__ float g_y[G_DIM * C_DIM];                      // 8 MB
__device__ float g_yh[G_DIM * C_DIM];                     // 8 MB

#define MMA16816(d, a0, a1, a2, a3, b0, b1) \
    asm volatile("mma.sync.aligned.m16n8k16.row.col.f32.bf16.bf16.f32 " \
                 "{%0,%1,%2,%3}, {%4,%5,%6,%7}, {%8,%9}, {%0,%1,%2,%3};" \
                 : "+f"((d)[0]), "+f"((d)[1]), "+f"((d)[2]), "+f"((d)[3]) \
                 : "r"(a0), "r"(a1), "r"(a2), "r"(a3), "r"(b0), "r"(b1))

__device__ __forceinline__ uint32_t smem_u32(const void* p) {
    uint32_t a;
    asm("{ .reg .u64 t; cvta.to.shared.u64 t, %1; cvt.u32.u64 %0, t; }" : "=r"(a) : "l"(p));
    return a;
}
__device__ __forceinline__ void cp16(uint32_t saddr, const void* g) {
    asm volatile("cp.async.cg.shared.global [%0], [%1], 16;" :: "r"(saddr), "l"(g));
}

// ---------------- zero accumulators ----------------
__global__ void zero_kernel() {
    int i = blockIdx.x * blockDim.x + threadIdx.x;   // G*C/4
    float4 z = make_float4(0.f, 0.f, 0.f, 0.f);
    ((float4*)g_denom)[i] = z;
    ((float4*)g_y)[i] = z;
}

// ---------------- denom -> 1/denom (between the two gemm halves) ----------------
__global__ void rcp_kernel() {
    int i = blockIdx.x * blockDim.x + threadIdx.x;   // G*C/4
    float4 d = ((float4*)g_denom)[i];
    d.x = 1.0f / d.x;
    d.y = 1.0f / d.y;
    d.z = 1.0f / d.z;
    d.w = 1.0f / d.w;
    ((float4*)g_denom)[i] = d;
}

// ---------------- build W in fragment-permuted layout ----------------
// Layout: [stripe(128 cols)][kchunk(32)][block = n16t*2 + s][granule l][word w][elem e]
//   granule l: gid = l>>2, tig = l&3
//   word w: n8 = w&1, khalf = w>>1
//   n = stripe*128 + n16t*16 + n8*8 + gid
//   k = kchunk*32 + s*16 + 2*tig + khalf*8 + e
// Per (stripe,kchunk) tile = 4096 bf16 = 8192 B, cp.async-able as 512 x 16B.
__device__ __forceinline__ void decode_frag_idx(int i, int& n, int& k) {
    int stripe = i >> 16;
    int r = i & 65535;
    int kchunk = r >> 12;
    int r2 = r & 4095;
    int block = r2 >> 8;
    int r3 = r2 & 255;
    int gran = r3 >> 3;
    int w = (r3 >> 1) & 3;
    int e = r3 & 1;
    int n16t = block >> 1, s = block & 1;
    int gid = gran >> 2, tig = gran & 3;
    n = stripe * 128 + n16t * 16 + (w & 1) * 8 + gid;
    k = kchunk * 32 + s * 16 + 2 * tig + (w >> 1) * 8 + e;
}

__global__ void build_w_kernel(const float* __restrict__ Wf,
                               const float* __restrict__ Wg) {
    int i = blockIdx.x * blockDim.x + threadIdx.x;   // NOUT*C_DIM
    int n, k;
    decode_frag_idx(i, n, k);
    const float* W = (n < 512) ? Wf : Wg;
    float w = W[(size_t)k * C_DIM + (n & 511)];
    __nv_bfloat16 hi = __float2bfloat16(w);
    g_whi[i] = hi;
    g_wlo[i] = __float2bfloat16(w - __bfloat162float(hi));
}

__global__ void build_wh_kernel(const float* __restrict__ Wh) {
    int i = blockIdx.x * blockDim.x + threadIdx.x;   // C_DIM*C_DIM
    int n, k;
    decode_frag_idx(i, n, k);
    float w = Wh[(size_t)k * C_DIM + n];
    __nv_bfloat16 hi = __float2bfloat16(w);
    g_whh[i] = hi;
    g_wlh[i] = __float2bfloat16(w - __bfloat162float(hi));
}

// ---------------- mma.sync bf16-split GEMM (R14 config: BM=128, 2 CTA/SM) ------
// A: fragment-contiguous smem (R14). B: fragment-permuted gmem -> verbatim
// cp.async -> 4x LDS.128 per k-step (was 16x LDS.32).
#define A_TILE_BYTES 8448               // 16 blocks * 528B (128 rows)
#define B_TILE_BYTES 8192               // 16 blocks * 512B (128 cols x 32 k)
#define STG_BYTES (2 * A_TILE_BYTES + 2 * B_TILE_BYTES)   // 33280
#define B_OFF (2 * A_TILE_BYTES)

#define PRECOMP_A_OFFS()                                                      \
    uint32_t aoff[4][2];                                                      \
    _Pragma("unroll")                                                         \
    for (int i_ = 0; i_ < 4; i_++) {                                          \
        int u_ = tid + 256 * i_;                                              \
        int r_ = u_ >> 3, sq_ = u_ & 7;                                       \
        _Pragma("unroll")                                                     \
        for (int q_ = 0; q_ < 2; q_++) {                                      \
            int w_ = 2 * sq_ + q_;                                            \
            int s_ = w_ >> 3, rem_ = w_ & 7;                                  \
            int tg_ = rem_ & 3, kk_ = rem_ >> 2;                              \
            aoff[i_][q_] = (uint32_t)(((r_ >> 4) * 2 + s_) * 528 +            \
                                      ((r_ & 7) * 4 + tg_) * 16 +             \
                                      kk_ * 8 + ((r_ >> 3) & 1) * 4);         \
        }                                                                     \
    }

#define LOAD_A_IMPL(SRC, CH) do {                                             \
        const int kc_ = (CH) * 32;                                            \
        _Pragma("unroll")                                                     \
        for (int i_ = 0; i_ < 4; i_++) {                                      \
            int u_ = tid + i_ * 256;                                          \
            int r_ = u_ >> 3, s_ = u_ & 7;                                    \
            stg[i_] = *(const float4*)((SRC) + (size_t)(row0 + r_) * C_DIM + kc_ + s_ * 4); \
        }                                                                     \
    } while (0)

#define STORE_A_IMPL(BUF) do {                                                \
        char* ahi_ = (char*)sm + (BUF) * STG_BYTES;                           \
        char* alo_ = ahi_ + A_TILE_BYTES;                                     \
        _Pragma("unroll")                                                     \
        for (int i_ = 0; i_ < 4; i_++) {                                      \
            float4 v_ = stg[i_];                                              \
            __nv_bfloat162 h01_, h23_, l01_, l23_;                            \
            h01_.x = __float2bfloat16(v_.x); h01_.y = __float2bfloat16(v_.y); \
            h23_.x = __float2bfloat16(v_.z); h23_.y = __float2bfloat16(v_.w); \
            l01_.x = __float2bfloat16(v_.x - __bfloat162float(h01_.x));       \
            l01_.y = __float2bfloat16(v_.y - __bfloat162float(h01_.y));       \
            l23_.x = __float2bfloat16(v_.z - __bfloat162float(h23_.x));       \
            l23_.y = __float2bfloat16(v_.w - __bfloat162float(h23_.y));       \
            *(uint32_t*)(ahi_ + aoff[i_][0]) = *(uint32_t*)&h01_;             \
            *(uint32_t*)(ahi_ + aoff[i_][1]) = *(uint32_t*)&h23_;             \
            *(uint32_t*)(alo_ + aoff[i_][0]) = *(uint32_t*)&l01_;             \
            *(uint32_t*)(alo_ + aoff[i_][1]) = *(uint32_t*)&l23_;             \
        }                                                                     \
    } while (0)

// B tile: contiguous 8192B per hi/lo -> 512 16B chunks each; 2 per thread.
#define LOAD_B_IMPL(WH, WL, BUF, CH) do {                                     \
        uint32_t bhi_ = smem_u32((char*)sm + (BUF) * STG_BYTES + B_OFF);      \
        uint32_t blo_ = bhi_ + B_TILE_BYTES;                                  \
        const __nv_bfloat16* srcH = (WH) + wbase + (CH) * 4096;               \
        const __nv_bfloat16* srcL = (WL) + wbase + (CH) * 4096;               \
        _Pragma("unroll")                                                     \
        for (int i_ = 0; i_ < 2; i_++) {                                      \
            int u_ = tid + i_ * 256;                                          \
            cp16(bhi_ + u_ * 16, srcH + u_ * 8);                              \
            cp16(blo_ + u_ * 16, srcL + u_ * 8);                              \
        }                                                                     \
        asm volatile("cp.async.commit_group;" ::: "memory");                  \
    } while (0)

#define MAINLOOP_BODY(ASRC, WH, WL)                                           \
    LOAD_B_IMPL(WH, WL, 0, 0);                                                \
    LOAD_A_IMPL(ASRC, 0);                                                     \
    STORE_A_IMPL(0);                                                          \
    asm volatile("cp.async.wait_group 0;" ::: "memory");                      \
    __syncthreads();                                                          \
    for (int it = 0; it < 16; it++) {                                         \
        const int cur = it & 1;                                               \
        if (it + 1 < 16) {                                                    \
            LOAD_B_IMPL(WH, WL, cur ^ 1, it + 1);                             \
            LOAD_A_IMPL(ASRC, it + 1);                                        \
        }                                                                     \
        const char* Ab = (const char*)sm + cur * STG_BYTES;                   \
        const char* Bb = Ab + B_OFF;                                          \
        _Pragma("unroll")                                                     \
        for (int s = 0; s < 2; s++) {                                         \
            uint32_t bH[4][2], bL[4][2];                                      \
            _Pragma("unroll")                                                 \
            for (int p = 0; p < 2; p++) {                                     \
                const uint32_t boff = (uint32_t)(((wn * 2 + p) * 2 + s) * 512 + l * 16); \
                uint4 fH = *(const uint4*)(Bb + boff);                        \
                uint4 fL = *(const uint4*)(Bb + B_TILE_BYTES + boff);         \
                bH[2*p][0] = fH.x; bH[2*p+1][0] = fH.y;                       \
                bH[2*p][1] = fH.z; bH[2*p+1][1] = fH.w;                       \
                bL[2*p][0] = fL.x; bL[2*p+1][0] = fL.y;                       \
                bL[2*p][1] = fL.z; bL[2*p+1][1] = fL.w;                       \
            }                                                                 \
            _Pragma("unroll")                                                 \
            for (int t = 0; t < 4; t++) {                                     \
                const uint32_t ar = (uint32_t)((((wm * 4 + t) * 2 + s) * 528) + l * 16); \
                uint4 qh = *(const uint4*)(Ab + ar);                          \
                uint4 ql = *(const uint4*)(Ab + A_TILE_BYTES + ar);           \
                _Pragma("unroll")                                             \
                for (int nt = 0; nt < 4; nt++)                                \
                    MMA16816(acc[t][nt], qh.x, qh.y, qh.z, qh.w,              \
                             bH[nt][0], bH[nt][1]);                           \
                _Pragma("unroll")                                             \
                for (int nt = 0; nt < 4; nt++)                                \
                    MMA16816(acc[t][nt], qh.x, qh.y, qh.z, qh.w,              \
                             bL[nt][0], bL[nt][1]);                           \
                _Pragma("unroll")                                             \
                for (int nt = 0; nt < 4; nt++)                                \
                    MMA16816(acc[t][nt], ql.x, ql.y, ql.z, ql.w,              \
                             bH[nt][0], bH[nt][1]);                           \
            }                                                                 \
        }                                                                     \
        if (it + 1 < 16) {                                                    \
            STORE_A_IMPL(cur ^ 1);                                            \
            asm volatile("cp.async.wait_group 0;" ::: "memory");              \
        }                                                                     \
        __syncthreads();                                                      \
    }

template <bool IS_G>
__global__ __launch_bounds__(256, 2)
void gemm_half(const float* __restrict__ x, const int* __restrict__ ix,
               const float* __restrict__ bias) {
    extern __shared__ __nv_bfloat16 sm[];

    const int tid  = threadIdx.x;
    const int l    = tid & 31;
    const int warp = tid >> 5;
    const int bx   = blockIdx.x;          // 0..3 -> 128-col stripe of this half
    const int row0 = blockIdx.y * 128;
    const int n0g  = (IS_G ? 512 : 0) + bx * 128;
    const size_t wbase = (size_t)(n0g >> 7) * 65536;   // stripe base in permuted W

    const int wm = warp >> 2;
    const int wn = warp & 3;
    const int m_base = wm * 64;
    const int n_base = wn * 32;
    const int gid = l >> 2, tig = l & 3;

    float acc[4][4][4];
#pragma unroll
    for (int t = 0; t < 4; t++)
#pragma unroll
        for (int n = 0; n < 4; n++)
#pragma unroll
            for (int r = 0; r < 4; r++) acc[t][n][r] = 0.f;

    float4 stg[4];
    PRECOMP_A_OFFS()

    MAINLOOP_BODY(x, g_whi, g_wlo)

    // ---- epilogue (R14 exact) ----
#pragma unroll
    for (int t = 0; t < 4; t++) {
#pragma unroll
        for (int h = 0; h < 2; h++) {
            const int m = row0 + m_base + t * 16 + gid + h * 8;
            const int grp = ix[m];
#pragma unroll
            for (int nt = 0; nt < 4; nt++) {
                const int cg = n0g + n_base + nt * 8 + 2 * tig;
                const int cw = cg & 511;
                float v0 = acc[t][nt][2 * h]     + bias[cw];
                float v1 = acc[t][nt][2 * h + 1] + bias[cw + 1];
                if (IS_G) {
                    v0 = __expf(v0);
                    v1 = __expf(v1);
                    __half2 eq = __floats2half2_rn(v0, v1);
                    *(__half2*)&g_eg[(size_t)m * C_DIM + cw] = eq;
                    float q0 = __half2float(__low2half(eq));
                    float q1 = __half2float(__high2half(eq));
                    float* dp = &g_denom[(size_t)grp * C_DIM + cw];
                    atomicAdd(dp,     q0);
                    atomicAdd(dp + 1, q1);
                } else {
                    __half2 eh = *(const __half2*)&g_eg[(size_t)m * C_DIM + cw];
                    float2 e = __half22float2(eh);
                    float2 d = *(const float2*)&g_denom[(size_t)grp * C_DIM + cw]; // reciprocal
                    float* yp = &g_y[(size_t)grp * C_DIM + cw];
                    atomicAdd(yp,     v0 * e.x * d.x);
                    atomicAdd(yp + 1, v1 * e.y * d.y);
                }
            }
        }
    }
}

// ---------------- yh = y @ Wh + bh via bf16-split mma (same mainloop) ----------
__global__ __launch_bounds__(256, 2)
void gemm_h_mma(const float* __restrict__ bh) {
    extern __shared__ __nv_bfloat16 sm[];

    const int tid  = threadIdx.x;
    const int l    = tid & 31;
    const int warp = tid >> 5;
    const int bx   = blockIdx.x;          // 0..3 -> 128-col stripe of 512
    const int row0 = blockIdx.y * 128;    // 0..31 row blocks of G_DIM
    const int n0g  = bx * 128;
    const size_t wbase = (size_t)(n0g >> 7) * 65536;

    const int wm = warp >> 2;
    const int wn = warp & 3;
    const int m_base = wm * 64;
    const int n_base = wn * 32;
    const int gid = l >> 2, tig = l & 3;

    float acc[4][4][4];
#pragma unroll
    for (int t = 0; t < 4; t++)
#pragma unroll
        for (int n = 0; n < 4; n++)
#pragma unroll
            for (int r = 0; r < 4; r++) acc[t][n][r] = 0.f;

    float4 stg[4];
    PRECOMP_A_OFFS()

    MAINLOOP_BODY(g_y, g_whh, g_wlh)

    // ---- epilogue: bias + store ----
#pragma unroll
    for (int t = 0; t < 4; t++) {
#pragma unroll
        for (int h = 0; h < 2; h++) {
            const int m = row0 + m_base + t * 16 + gid + h * 8;
#pragma unroll
            for (int nt = 0; nt < 4; nt++) {
                const int cw = n0g + n_base + nt * 8 + 2 * tig;
                float v0 = acc[t][nt][2 * h]     + bh[cw];
                float v1 = acc[t][nt][2 * h + 1] + bh[cw + 1];
                *(float2*)&g_yh[(size_t)m * C_DIM + cw] = make_float2(v0, v1);
            }
        }
    }
}

// ---------------- out[n] = yh[ix[n]] ----------------
__global__ void gather_kernel(const int* __restrict__ ix, float* __restrict__ out) {
    size_t idx = (size_t)blockIdx.x * blockDim.x + threadIdx.x;  // N*C/4
    int n  = (int)(idx >> 7);
    int cq = (int)(idx & 127) << 2;
    int g  = ix[n];
    *(float4*)&out[((size_t)n << 9) + cq] = *(const float4*)&g_yh[((size_t)g << 9) + cq];
}

extern "C" void kernel_launch(void* const* d_in, const int* in_sizes, int n_in,
                              void* d_out, int out_size) {
    const float* x  = (const float*)d_in[0];
    const int*   ix = (const int*)d_in[1];
    const float* Wf = (const float*)d_in[2];
    const float* bf = (const float*)d_in[3];
    const float* Wg = (const float*)d_in[4];
    const float* bg = (const float*)d_in[5];
    const float* Wh = (const float*)d_in[6];
    const float* bh = (const float*)d_in[7];
    float* out = (float*)d_out;

    const int SMEM = 2 * STG_BYTES;   // 66560 bytes
    cudaFuncSetAttribute(gemm_half<true>,  cudaFuncAttributeMaxDynamicSharedMemorySize, SMEM);
    cudaFuncSetAttribute(gemm_half<false>, cudaFuncAttributeMaxDynamicSharedMemorySize, SMEM);
    cudaFuncSetAttribute(gemm_h_mma,       cudaFuncAttributeMaxDynamicSharedMemorySize, SMEM);

    zero_kernel<<<(G_DIM * C_DIM / 4) / 256, 256>>>();
    build_w_kernel<<<(NOUT * C_DIM) / 256, 256>>>(Wf, Wg);
    build_wh_kernel<<<(C_DIM * C_DIM) / 256, 256>>>(Wh);

    dim3 g1(4, N_ELEM / 128);
    gemm_half<true><<<g1, 256, SMEM>>>(x, ix, bg);    // eg(fp16) + denom
    rcp_kernel<<<(G_DIM * C_DIM / 4) / 256, 256>>>(); // denom -> 1/denom
    gemm_half<false><<<g1, 256, SMEM>>>(x, ix, bf);   // fx, fused aggregation

    dim3 g2(4, G_DIM / 128);
    gemm_h_mma<<<g2, 256, SMEM>>>(bh);

    gather_kernel<<<(N_ELEM * (C_DIM / 4)) / 256, 256>>>(ix, out);
}

// round 17
// speedup vs baseline: 1.1155x; 1.0427x over previous
#include <cuda_runtime.h>
#include <cuda_bf16.h>
#include <cuda_fp16.h>
#include <math.h>
#include <stdint.h>

#define N_ELEM 131072
#define C_DIM  512
#define G_DIM  4096
#define NOUT   1024     // fused: 8 stripes x (64 Wf cols || 64 Wg cols)

// ---------------- scratch (device globals; no allocation allowed) ----------------
// W buffers stored FRAGMENT-PERMUTED (see build_w_kernel).
__device__ __nv_bfloat16 g_whi[(size_t)NOUT * C_DIM];     // 1 MB
__device__ __nv_bfloat16 g_wlo[(size_t)NOUT * C_DIM];     // 1 MB
__device__ __nv_bfloat16 g_whh[(size_t)C_DIM * C_DIM];    // 0.5 MB (Wh hi)
__device__ __nv_bfloat16 g_wlh[(size_t)C_DIM * C_DIM];    // 0.5 MB (Wh lo)
__device__ float g_denom[G_DIM * C_DIM];                  // 8 MB
__device__ float g_y[G_DIM * C_DIM];                      // 8 MB (numer, then y)
__device__ float g_yh[G_DIM * C_DIM];                     // 8 MB

#define MMA16816(d, a0, a1, a2, a3, b0, b1) \
    asm volatile("mma.sync.aligned.m16n8k16.row.col.f32.bf16.bf16.f32 " \
                 "{%0,%1,%2,%3}, {%4,%5,%6,%7}, {%8,%9}, {%0,%1,%2,%3};" \
                 : "+f"((d)[0]), "+f"((d)[1]), "+f"((d)[2]), "+f"((d)[3]) \
                 : "r"(a0), "r"(a1), "r"(a2), "r"(a3), "r"(b0), "r"(b1))

__device__ __forceinline__ uint32_t smem_u32(const void* p) {
    uint32_t a;
    asm("{ .reg .u64 t; cvta.to.shared.u64 t, %1; cvt.u32.u64 %0, t; }" : "=r"(a) : "l"(p));
    return a;
}
__device__ __forceinline__ void cp16(uint32_t saddr, const void* g) {
    asm volatile("cp.async.cg.shared.global [%0], [%1], 16;" :: "r"(saddr), "l"(g));
}

// ---------------- zero accumulators ----------------
__global__ void zero_kernel() {
    int i = blockIdx.x * blockDim.x + threadIdx.x;   // G*C/4
    float4 z = make_float4(0.f, 0.f, 0.f, 0.f);
    ((float4*)g_denom)[i] = z;
    ((float4*)g_y)[i] = z;
}

// ---------------- y = numer / denom ----------------
__global__ void div_kernel() {
    int i = blockIdx.x * blockDim.x + threadIdx.x;   // G*C/4
    float4 n = ((float4*)g_y)[i];
    float4 d = ((float4*)g_denom)[i];
    n.x /= d.x; n.y /= d.y; n.z /= d.z; n.w /= d.w;
    ((float4*)g_y)[i] = n;
}

// ---------------- build W in fragment-permuted layout ----------------
// Permuted index -> (n_perm in [0,1024), k). Stripe = n_perm>>7 (8 stripes of
// 128 local cols). Local col loc = n_perm&127: loc<64 -> Wf col stripe*64+loc,
// loc>=64 -> Wg col stripe*64+(loc-64). Per (stripe,kchunk) tile = 8192 B.
__device__ __forceinline__ void decode_frag_idx(int i, int& n, int& k) {
    int stripe = i >> 16;
    int r = i & 65535;
    int kchunk = r >> 12;
    int r2 = r & 4095;
    int block = r2 >> 8;
    int r3 = r2 & 255;
    int gran = r3 >> 3;
    int w = (r3 >> 1) & 3;
    int e = r3 & 1;
    int n16t = block >> 1, s = block & 1;
    int gid = gran >> 2, tig = gran & 3;
    n = stripe * 128 + n16t * 16 + (w & 1) * 8 + gid;
    k = kchunk * 32 + s * 16 + 2 * tig + (w >> 1) * 8 + e;
}

__global__ void build_w_kernel(const float* __restrict__ Wf,
                               const float* __restrict__ Wg) {
    int i = blockIdx.x * blockDim.x + threadIdx.x;   // NOUT*C_DIM
    int n, k;
    decode_frag_idx(i, n, k);
    int stripe = n >> 7, loc = n & 127;
    const float* W = (loc < 64) ? Wf : Wg;
    int col = stripe * 64 + (loc & 63);
    float w = W[(size_t)k * C_DIM + col];
    __nv_bfloat16 hi = __float2bfloat16(w);
    g_whi[i] = hi;
    g_wlo[i] = __float2bfloat16(w - __bfloat162float(hi));
}

__global__ void build_wh_kernel(const float* __restrict__ Wh) {
    int i = blockIdx.x * blockDim.x + threadIdx.x;   // C_DIM*C_DIM
    int n, k;
    decode_frag_idx(i, n, k);
    float w = Wh[(size_t)k * C_DIM + n];
    __nv_bfloat16 hi = __float2bfloat16(w);
    g_whh[i] = hi;
    g_wlh[i] = __float2bfloat16(w - __bfloat162float(hi));
}

// ---------------- fused mma.sync bf16-split GEMM (R16 mainloop) ----------------
#define A_TILE_BYTES 8448               // 16 blocks * 528B (128 rows)
#define B_TILE_BYTES 8192               // 16 blocks * 512B
#define STG_BYTES (2 * A_TILE_BYTES + 2 * B_TILE_BYTES)   // 33280
#define B_OFF (2 * A_TILE_BYTES)

#define PRECOMP_A_OFFS()                                                      \
    uint32_t aoff[4][2];                                                      \
    _Pragma("unroll")                                                         \
    for (int i_ = 0; i_ < 4; i_++) {                                          \
        int u_ = tid + 256 * i_;                                              \
        int r_ = u_ >> 3, sq_ = u_ & 7;                                       \
        _Pragma("unroll")                                                     \
        for (int q_ = 0; q_ < 2; q_++) {                                      \
            int w_ = 2 * sq_ + q_;                                            \
            int s_ = w_ >> 3, rem_ = w_ & 7;                                  \
            int tg_ = rem_ & 3, kk_ = rem_ >> 2;                              \
            aoff[i_][q_] = (uint32_t)(((r_ >> 4) * 2 + s_) * 528 +            \
                                      ((r_ & 7) * 4 + tg_) * 16 +             \
                                      kk_ * 8 + ((r_ >> 3) & 1) * 4);         \
        }                                                                     \
    }

#define LOAD_A_IMPL(SRC, CH) do {                                             \
        const int kc_ = (CH) * 32;                                            \
        _Pragma("unroll")                                                     \
        for (int i_ = 0; i_ < 4; i_++) {                                      \
            int u_ = tid + i_ * 256;                                          \
            int r_ = u_ >> 3, s_ = u_ & 7;                                    \
            stg[i_] = *(const float4*)((SRC) + (size_t)(row0 + r_) * C_DIM + kc_ + s_ * 4); \
        }                                                                     \
    } while (0)

#define STORE_A_IMPL(BUF) do {                                                \
        char* ahi_ = (char*)sm + (BUF) * STG_BYTES;                           \
        char* alo_ = ahi_ + A_TILE_BYTES;                                     \
        _Pragma("unroll")                                                     \
        for (int i_ = 0; i_ < 4; i_++) {                                      \
            float4 v_ = stg[i_];                                              \
            __nv_bfloat162 h01_, h23_, l01_, l23_;                            \
            h01_.x = __float2bfloat16(v_.x); h01_.y = __float2bfloat16(v_.y); \
            h23_.x = __float2bfloat16(v_.z); h23_.y = __float2bfloat16(v_.w); \
            l01_.x = __float2bfloat16(v_.x - __bfloat162float(h01_.x));       \
            l01_.y = __float2bfloat16(v_.y - __bfloat162float(h01_.y));       \
            l23_.x = __float2bfloat16(v_.z - __bfloat162float(h23_.x));       \
            l23_.y = __float2bfloat16(v_.w - __bfloat162float(h23_.y));       \
            *(uint32_t*)(ahi_ + aoff[i_][0]) = *(uint32_t*)&h01_;             \
            *(uint32_t*)(ahi_ + aoff[i_][1]) = *(uint32_t*)&h23_;             \
            *(uint32_t*)(alo_ + aoff[i_][0]) = *(uint32_t*)&l01_;             \
            *(uint32_t*)(alo_ + aoff[i_][1]) = *(uint32_t*)&l23_;             \
        }                                                                     \
    } while (0)

#define LOAD_B_IMPL(WH, WL, BUF, CH) do {                                     \
        uint32_t bhi_ = smem_u32((char*)sm + (BUF) * STG_BYTES + B_OFF);      \
        uint32_t blo_ = bhi_ + B_TILE_BYTES;                                  \
        const __nv_bfloat16* srcH = (WH) + wbase + (CH) * 4096;               \
        const __nv_bfloat16* srcL = (WL) + wbase + (CH) * 4096;               \
        _Pragma("unroll")                                                     \
        for (int i_ = 0; i_ < 2; i_++) {                                      \
            int u_ = tid + i_ * 256;                                          \
            cp16(bhi_ + u_ * 16, srcH + u_ * 8);                              \
            cp16(blo_ + u_ * 16, srcL + u_ * 8);                              \
        }                                                                     \
        asm volatile("cp.async.commit_group;" ::: "memory");                  \
    } while (0)

#define MAINLOOP_BODY(ASRC, WH, WL)                                           \
    LOAD_B_IMPL(WH, WL, 0, 0);                                                \
    LOAD_A_IMPL(ASRC, 0);                                                     \
    STORE_A_IMPL(0);                                                          \
    asm volatile("cp.async.wait_group 0;" ::: "memory");                      \
    __syncthreads();                                                          \
    for (int it = 0; it < 16; it++) {                                         \
        const int cur = it & 1;                                               \
        if (it + 1 < 16) {                                                    \
            LOAD_B_IMPL(WH, WL, cur ^ 1, it + 1);                             \
            LOAD_A_IMPL(ASRC, it + 1);                                        \
        }                                                                     \
        const char* Ab = (const char*)sm + cur * STG_BYTES;                   \
        const char* Bb = Ab + B_OFF;                                          \
        _Pragma("unroll")                                                     \
        for (int s = 0; s < 2; s++) {                                         \
            uint32_t bH[4][2], bL[4][2];                                      \
            _Pragma("unroll")                                                 \
            for (int p = 0; p < 2; p++) {                                     \
                const uint32_t boff = (uint32_t)(((wn * 2 + p) * 2 + s) * 512 + l * 16); \
                uint4 fH = *(const uint4*)(Bb + boff);                        \
                uint4 fL = *(const uint4*)(Bb + B_TILE_BYTES + boff);         \
                bH[2*p][0] = fH.x; bH[2*p+1][0] = fH.y;                       \
                bH[2*p][1] = fH.z; bH[2*p+1][1] = fH.w;                       \
                bL[2*p][0] = fL.x; bL[2*p+1][0] = fL.y;                       \
                bL[2*p][1] = fL.z; bL[2*p+1][1] = fL.w;                       \
            }                                                                 \
            _Pragma("unroll")                                                 \
            for (int t = 0; t < 4; t++) {                                     \
                const uint32_t ar = (uint32_t)((((wm * 4 + t) * 2 + s) * 528) + l * 16); \
                uint4 qh = *(const uint4*)(Ab + ar);                          \
                uint4 ql = *(const uint4*)(Ab + A_TILE_BYTES + ar);           \
                _Pragma("unroll")                                             \
                for (int nt = 0; nt < 4; nt++)                                \
                    MMA16816(acc[t][nt], qh.x, qh.y, qh.z, qh.w,              \
                             bH[nt][0], bH[nt][1]);                           \
                _Pragma("unroll")                                             \
                for (int nt = 0; nt < 4; nt++)                                \
                    MMA16816(acc[t][nt], qh.x, qh.y, qh.z, qh.w,              \
                             bL[nt][0], bL[nt][1]);                           \
                _Pragma("unroll")                                             \
                for (int nt = 0; nt < 4; nt++)                                \
                    MMA16816(acc[t][nt], ql.x, ql.y, ql.z, ql.w,              \
                             bH[nt][0], bH[nt][1]);                           \
            }                                                                 \
        }                                                                     \
        if (it + 1 < 16) {                                                    \
            STORE_A_IMPL(cur ^ 1);                                            \
            asm volatile("cp.async.wait_group 0;" ::: "memory");              \
        }                                                                     \
        __syncthreads();                                                      \
    }

// Fused kernel: tile = 64 Wf cols (warps wn 0,1) || 64 Wg cols (warps wn 2,3),
// SAME global columns. eg warp (wm, wn+2) fragment (t,h,nt,q) pairs exactly
// with fx warp (wm, wn) fragment (t,h,nt,q): same m, same global col.
// Epilogue: eg warps exp -> smem exchange + denom atomics; fx warps read
// partner eg, atomicAdd numer += fx*eg.
__global__ __launch_bounds__(256, 2)
void gemm_fused(const float* __restrict__ x, const int* __restrict__ ix,
                const float* __restrict__ bf, const float* __restrict__ bg) {
    extern __shared__ __nv_bfloat16 sm[];

    const int tid  = threadIdx.x;
    const int l    = tid & 31;
    const int warp = tid >> 5;
    const int bx   = blockIdx.x;          // 0..7 stripe
    const int row0 = blockIdx.y * 128;
    const size_t wbase = (size_t)bx * 65536;

    const int wm = warp >> 2;
    const int wn = warp & 3;
    const int m_base = wm * 64;
    const int gid = l >> 2, tig = l & 3;

    float acc[4][4][4];
#pragma unroll
    for (int t = 0; t < 4; t++)
#pragma unroll
        for (int n = 0; n < 4; n++)
#pragma unroll
            for (int r = 0; r < 4; r++) acc[t][n][r] = 0.f;

    float4 stg[4];
    PRECOMP_A_OFFS()

    MAINLOOP_BODY(x, g_whi, g_wlo)

    // ---- fused epilogue ----
    const bool isG = (wn >= 2);
    const int region = wm * 2 + (wn & 1);      // pairing region 0..3
    float* exch = (float*)sm;                  // 4 regions * 2048 floats = 32KB

    if (isG) {
        // compute exp in-place, stash to exchange
#pragma unroll
        for (int t = 0; t < 4; t++)
#pragma unroll
            for (int h = 0; h < 2; h++)
#pragma unroll
                for (int nt = 0; nt < 4; nt++) {
                    const int cl = (wn - 2) * 32 + nt * 8 + 2 * tig; // 0..63
                    const int cg = bx * 64 + cl;
                    float v0 = __expf(acc[t][nt][2 * h]     + bg[cg]);
                    float v1 = __expf(acc[t][nt][2 * h + 1] + bg[cg + 1]);
                    acc[t][nt][2 * h]     = v0;
                    acc[t][nt][2 * h + 1] = v1;
                    const int idx = ((t * 2 + h) * 4 + nt) * 2;
                    exch[region * 2048 + idx * 32 + l]        = v0;
                    exch[region * 2048 + (idx + 1) * 32 + l]  = v1;
                }
    }
    __syncthreads();

    if (isG) {
        // denom atomics
#pragma unroll
        for (int t = 0; t < 4; t++)
#pragma unroll
            for (int h = 0; h < 2; h++) {
                const int m = row0 + m_base + t * 16 + gid + h * 8;
                const int grp = ix[m];
#pragma unroll
                for (int nt = 0; nt < 4; nt++) {
                    const int cg = bx * 64 + (wn - 2) * 32 + nt * 8 + 2 * tig;
                    float* dp = &g_denom[(size_t)grp * C_DIM + cg];
                    atomicAdd(dp,     acc[t][nt][2 * h]);
                    atomicAdd(dp + 1, acc[t][nt][2 * h + 1]);
                }
            }
    } else {
        // numer atomics: fx * eg(partner)
#pragma unroll
        for (int t = 0; t < 4; t++)
#pragma unroll
            for (int h = 0; h < 2; h++) {
                const int m = row0 + m_base + t * 16 + gid + h * 8;
                const int grp = ix[m];
#pragma unroll
                for (int nt = 0; nt < 4; nt++) {
                    const int cg = bx * 64 + wn * 32 + nt * 8 + 2 * tig;
                    const int idx = ((t * 2 + h) * 4 + nt) * 2;
                    float e0 = exch[region * 2048 + idx * 32 + l];
                    float e1 = exch[region * 2048 + (idx + 1) * 32 + l];
                    float f0 = acc[t][nt][2 * h]     + bf[cg];
                    float f1 = acc[t][nt][2 * h + 1] + bf[cg + 1];
                    float* yp = &g_y[(size_t)grp * C_DIM + cg];
                    atomicAdd(yp,     f0 * e0);
                    atomicAdd(yp + 1, f1 * e1);
                }
            }
    }
}

// ---------------- yh = y @ Wh + bh via bf16-split mma (same mainloop) ----------
__global__ __launch_bounds__(256, 2)
void gemm_h_mma(const float* __restrict__ bh) {
    extern __shared__ __nv_bfloat16 sm[];

    const int tid  = threadIdx.x;
    const int l    = tid & 31;
    const int warp = tid >> 5;
    const int bx   = blockIdx.x;          // 0..3 -> 128-col stripe of 512
    const int row0 = blockIdx.y * 128;
    const size_t wbase = (size_t)bx * 65536;

    const int wm = warp >> 2;
    const int wn = warp & 3;
    const int m_base = wm * 64;
    const int n_base = wn * 32;
    const int gid = l >> 2, tig = l & 3;

    float acc[4][4][4];
#pragma unroll
    for (int t = 0; t < 4; t++)
#pragma unroll
        for (int n = 0; n < 4; n++)
#pragma unroll
            for (int r = 0; r < 4; r++) acc[t][n][r] = 0.f;

    float4 stg[4];
    PRECOMP_A_OFFS()

    MAINLOOP_BODY(g_y, g_whh, g_wlh)

    // ---- epilogue: bias + store ----
#pragma unroll
    for (int t = 0; t < 4; t++) {
#pragma unroll
        for (int h = 0; h < 2; h++) {
            const int m = row0 + m_base + t * 16 + gid + h * 8;
#pragma unroll
            for (int nt = 0; nt < 4; nt++) {
                const int cw = bx * 128 + n_base + nt * 8 + 2 * tig;
                float v0 = acc[t][nt][2 * h]     + bh[cw];
                float v1 = acc[t][nt][2 * h + 1] + bh[cw + 1];
                *(float2*)&g_yh[(size_t)m * C_DIM + cw] = make_float2(v0, v1);
            }
        }
    }
}

// ---------------- out[n] = yh[ix[n]] ----------------
__global__ void gather_kernel(const int* __restrict__ ix, float* __restrict__ out) {
    size_t idx = (size_t)blockIdx.x * blockDim.x + threadIdx.x;  // N*C/4
    int n  = (int)(idx >> 7);
    int cq = (int)(idx & 127) << 2;
    int g  = ix[n];
    *(float4*)&out[((size_t)n << 9) + cq] = *(const float4*)&g_yh[((size_t)g << 9) + cq];
}

extern "C" void kernel_launch(void* const* d_in, const int* in_sizes, int n_in,
                              void* d_out, int out_size) {
    const float* x  = (const float*)d_in[0];
    const int*   ix = (const int*)d_in[1];
    const float* Wf = (const float*)d_in[2];
    const float* bf = (const float*)d_in[3];
    const float* Wg = (const float*)d_in[4];
    const float* bg = (const float*)d_in[5];
    const float* Wh = (const float*)d_in[6];
    const float* bh = (const float*)d_in[7];
    float* out = (float*)d_out;

    const int SMEM = 2 * STG_BYTES;   // 66560 bytes
    cudaFuncSetAttribute(gemm_fused, cudaFuncAttributeMaxDynamicSharedMemorySize, SMEM);
    cudaFuncSetAttribute(gemm_h_mma, cudaFuncAttributeMaxDynamicSharedMemorySize, SMEM);

    zero_kernel<<<(G_DIM * C_DIM / 4) / 256, 256>>>();
    build_w_kernel<<<(NOUT * C_DIM) / 256, 256>>>(Wf, Wg);
    build_wh_kernel<<<(C_DIM * C_DIM) / 256, 256>>>(Wh);

    dim3 g1(8, N_ELEM / 128);
    gemm_fused<<<g1, 256, SMEM>>>(x, ix, bf, bg);     // denom + numer in one pass

    div_kernel<<<(G_DIM * C_DIM / 4) / 256, 256>>>(); // y = numer / denom

    dim3 g2(4, G_DIM / 128);
    gemm_h_mma<<<g2, 256, SMEM>>>(bh);

    gather_kernel<<<(N_ELEM * (C_DIM / 4)) / 256, 256>>>(ix, out);
}